// round 1
// baseline (speedup 1.0000x reference)
#include <cuda_runtime.h>
#include <math.h>

#define CN 1024
#define HN 512
#define VN 32000
#define BN 16
#define TN 256
#define SPW 8

// ------------------------- scratch (static device memory; no allocs) -------
__device__ float g_tmp[CN*HN];
__device__ float g_hs[CN*HN];
__device__ float g_ht[CN*HN];
__device__ float g_hp[CN*HN];
__device__ float g_sl[CN];
__device__ float g_startlp[CN];
__device__ float g_trans[CN*CN];
__device__ float g_pair[VN*SPW];      // pair logits, later emission log-probs in-place
__device__ unsigned g_maxk[CN];
__device__ float g_sumb[CN];
__device__ float g_denom[CN];
__device__ float g_ev[BN];

// monotonic float<->uint encoding for atomicMax on floats
__device__ __forceinline__ unsigned enc_f(float f){
    int i = __float_as_int(f);
    return (unsigned)(i ^ ((i >> 31) | 0x80000000));
}
__device__ __forceinline__ float dec_f(unsigned u){
    int i = (u & 0x80000000u) ? (int)(u ^ 0x80000000u) : ~(int)u;
    return __int_as_float(i);
}

// ---------------------------------------------------------------------------
// GEMM: out[m,n] = (res? res[m,n] : 0) + act( sum_k A[m,k]*W[n,k] + bias[n] )
// A: (M,K) row-major, W: (N,K) row-major (i.e. computes A @ W^T).
// 64x64 tile, 4x4 micro, 256 threads. M,N multiples of 64; K multiple of 16.
// ---------------------------------------------------------------------------
__global__ __launch_bounds__(256) void gemm64(
    const float* __restrict__ A, const float* __restrict__ W,
    const float* __restrict__ bias, const float* __restrict__ res,
    float* __restrict__ out, int K, int N, int do_relu)
{
    __shared__ float As[16][68];
    __shared__ float Ws[16][68];
    int tid = threadIdx.x;
    int tx = tid & 15, ty = tid >> 4;
    int row0 = blockIdx.y * 64, col0 = blockIdx.x * 64;
    int lr = tid >> 2;            // 0..63
    int lq = (tid & 3) << 2;      // 0,4,8,12
    const float* Ap = A + (size_t)(row0 + lr) * K;
    const float* Wp = W + (size_t)(col0 + lr) * K;

    float acc[4][4];
    #pragma unroll
    for (int i = 0; i < 4; i++)
        #pragma unroll
        for (int j = 0; j < 4; j++) acc[i][j] = 0.f;

    for (int k0 = 0; k0 < K; k0 += 16) {
        float4 a4 = *(const float4*)(Ap + k0 + lq);
        float4 w4 = *(const float4*)(Wp + k0 + lq);
        As[lq+0][lr] = a4.x; As[lq+1][lr] = a4.y; As[lq+2][lr] = a4.z; As[lq+3][lr] = a4.w;
        Ws[lq+0][lr] = w4.x; Ws[lq+1][lr] = w4.y; Ws[lq+2][lr] = w4.z; Ws[lq+3][lr] = w4.w;
        __syncthreads();
        #pragma unroll
        for (int kk = 0; kk < 16; kk++) {
            float4 av = *(const float4*)&As[kk][ty << 2];
            float4 wv = *(const float4*)&Ws[kk][tx << 2];
            float am[4] = {av.x, av.y, av.z, av.w};
            float wn[4] = {wv.x, wv.y, wv.z, wv.w};
            #pragma unroll
            for (int i = 0; i < 4; i++)
                #pragma unroll
                for (int j = 0; j < 4; j++)
                    acc[i][j] = fmaf(am[i], wn[j], acc[i][j]);
        }
        __syncthreads();
    }

    float bn[4] = {0.f, 0.f, 0.f, 0.f};
    if (bias) {
        float4 b4 = *(const float4*)(bias + col0 + (tx << 2));
        bn[0] = b4.x; bn[1] = b4.y; bn[2] = b4.z; bn[3] = b4.w;
    }
    #pragma unroll
    for (int i = 0; i < 4; i++) {
        int m = row0 + (ty << 2) + i;
        float o0 = acc[i][0] + bn[0];
        float o1 = acc[i][1] + bn[1];
        float o2 = acc[i][2] + bn[2];
        float o3 = acc[i][3] + bn[3];
        if (do_relu) {
            o0 = fmaxf(o0, 0.f); o1 = fmaxf(o1, 0.f);
            o2 = fmaxf(o2, 0.f); o3 = fmaxf(o3, 0.f);
        }
        if (res) {
            float4 r4 = *(const float4*)(res + (size_t)m * N + col0 + (tx << 2));
            o0 += r4.x; o1 += r4.y; o2 += r4.z; o3 += r4.w;
        }
        *(float4*)(out + (size_t)m * N + col0 + (tx << 2)) = make_float4(o0, o1, o2, o3);
    }
}

// ---------------------------------------------------------------------------
// start head: g_sl[c] = dot(g_hs[c,:], ow) + ob. grid=128 blocks, 8 warps each
// ---------------------------------------------------------------------------
__global__ __launch_bounds__(256) void start_head_k(
    const float* __restrict__ ow, const float* __restrict__ ob)
{
    int warp = threadIdx.x >> 5, lane = threadIdx.x & 31;
    int c = blockIdx.x * 8 + warp;
    const float4* h4 = (const float4*)(g_hs + (size_t)c * HN);
    const float4* w4 = (const float4*)ow;
    float s = 0.f;
    #pragma unroll
    for (int i = lane; i < HN/4; i += 32) {
        float4 a = h4[i], w = w4[i];
        s = fmaf(a.x, w.x, s); s = fmaf(a.y, w.y, s);
        s = fmaf(a.z, w.z, s); s = fmaf(a.w, w.w, s);
    }
    #pragma unroll
    for (int o = 16; o; o >>= 1) s += __shfl_xor_sync(0xffffffffu, s, o);
    if (lane == 0) g_sl[c] = s + ob[0];
}

// log_softmax over the 1024 start logits. 1 block of 1024 threads.
__global__ __launch_bounds__(1024) void lsm_start_k()
{
    __shared__ float red[32];
    __shared__ float bc;
    int t = threadIdx.x;
    float v = g_sl[t];
    float m = v;
    #pragma unroll
    for (int o = 16; o; o >>= 1) m = fmaxf(m, __shfl_xor_sync(0xffffffffu, m, o));
    if ((t & 31) == 0) red[t >> 5] = m;
    __syncthreads();
    if (t < 32) {
        float x = red[t];
        #pragma unroll
        for (int o = 16; o; o >>= 1) x = fmaxf(x, __shfl_xor_sync(0xffffffffu, x, o));
        if (t == 0) bc = x;
    }
    __syncthreads();
    m = bc;
    float e = __expf(v - m);
    float s = e;
    #pragma unroll
    for (int o = 16; o; o >>= 1) s += __shfl_xor_sync(0xffffffffu, s, o);
    __syncthreads();
    if ((t & 31) == 0) red[t >> 5] = s;
    __syncthreads();
    if (t < 32) {
        float x = red[t];
        #pragma unroll
        for (int o = 16; o; o >>= 1) x += __shfl_xor_sync(0xffffffffu, x, o);
        if (t == 0) bc = x;
    }
    __syncthreads();
    g_startlp[t] = v - m - __logf(bc);
}

// per-row log_softmax of g_trans (1024 rows x 1024). grid=1024, 256 threads.
__global__ __launch_bounds__(256) void lsm_rows_k()
{
    __shared__ float red[8];
    __shared__ float bc;
    int row = blockIdx.x, t = threadIdx.x;
    float4* p4 = (float4*)(g_trans + (size_t)row * CN);
    float4 v = p4[t];
    float m = fmaxf(fmaxf(v.x, v.y), fmaxf(v.z, v.w));
    #pragma unroll
    for (int o = 16; o; o >>= 1) m = fmaxf(m, __shfl_xor_sync(0xffffffffu, m, o));
    if ((t & 31) == 0) red[t >> 5] = m;
    __syncthreads();
    if (t < 8) {
        float x = red[t];
        #pragma unroll
        for (int o = 4; o; o >>= 1) x = fmaxf(x, __shfl_xor_sync(0xffu, x, o));
        if (t == 0) bc = x;
    }
    __syncthreads();
    m = bc;
    float e = __expf(v.x - m) + __expf(v.y - m) + __expf(v.z - m) + __expf(v.w - m);
    #pragma unroll
    for (int o = 16; o; o >>= 1) e += __shfl_xor_sync(0xffffffffu, e, o);
    __syncthreads();
    if ((t & 31) == 0) red[t >> 5] = e;
    __syncthreads();
    if (t < 8) {
        float x = red[t];
        #pragma unroll
        for (int o = 4; o; o >>= 1) x += __shfl_xor_sync(0xffu, x, o);
        if (t == 0) bc = x;
    }
    __syncthreads();
    float lz = m + __logf(bc);
    p4[t] = make_float4(v.x - lz, v.y - lz, v.z - lz, v.w - lz);
}

// ---------------------------------------------------------------------------
// term sparse stage
// ---------------------------------------------------------------------------
__global__ void init_k()
{
    int i = blockIdx.x * 256 + threadIdx.x;
    if (i < CN) { g_maxk[i] = 0u; g_sumb[i] = 0.f; }  // key 0 == -inf
}

// one block per word: dot(hp[c], term_ow[v]) + ob[v] for its 8 states
__global__ __launch_bounds__(256) void term_pair_k(
    const float* __restrict__ tow, const float* __restrict__ tob,
    const int* __restrict__ w2s)
{
    __shared__ float ws[HN];
    __shared__ int cs[SPW];
    int v = blockIdx.x, tid = threadIdx.x;
    for (int i = tid; i < HN/4; i += 256)
        ((float4*)ws)[i] = ((const float4*)(tow + (size_t)v * HN))[i];
    if (tid < SPW) cs[tid] = w2s[v * SPW + tid];
    __syncthreads();
    int warp = tid >> 5, lane = tid & 31;
    int c = cs[warp];
    const float4* h4 = (const float4*)(g_hp + (size_t)c * HN);
    const float4* w4 = (const float4*)ws;
    float s = 0.f;
    #pragma unroll
    for (int i = lane; i < HN/4; i += 32) {
        float4 a = h4[i], w = w4[i];
        s = fmaf(a.x, w.x, s); s = fmaf(a.y, w.y, s);
        s = fmaf(a.z, w.z, s); s = fmaf(a.w, w.w, s);
    }
    #pragma unroll
    for (int o = 16; o; o >>= 1) s += __shfl_xor_sync(0xffffffffu, s, o);
    if (lane == 0) {
        float logit = s + tob[v];
        g_pair[v * SPW + warp] = logit;
        bool dup = false;
        for (int k2 = 0; k2 < warp; k2++) if (cs[k2] == c) dup = true;
        if (!dup) atomicMax(&g_maxk[c], enc_f(logit));
    }
}

__global__ void term_sum_k(const int* __restrict__ w2s)
{
    int idx = blockIdx.x * 256 + threadIdx.x;
    if (idx >= VN * SPW) return;
    int v = idx >> 3, k = idx & 7;
    int c = w2s[idx];
    for (int k2 = 0; k2 < k; k2++) if (w2s[(v << 3) + k2] == c) return;
    atomicAdd(&g_sumb[c], __expf(g_pair[idx] - dec_f(g_maxk[c])));
}

__global__ void denom_k()
{
    int c = blockIdx.x * 256 + threadIdx.x;
    if (c < CN) g_denom[c] = dec_f(g_maxk[c]) + __logf(g_sumb[c]);
}

__global__ void elog_k(const int* __restrict__ w2s)
{
    int idx = blockIdx.x * 256 + threadIdx.x;
    if (idx >= VN * SPW) return;
    g_pair[idx] -= g_denom[w2s[idx]];  // now emission log-prob per (word, k)
}

// ---------------------------------------------------------------------------
// forward scan: one block per batch. Pre-gathers trans entries into smem,
// then 8 lanes run 255 sequential logsumexp steps with replicated alphas.
// ---------------------------------------------------------------------------
__global__ __launch_bounds__(256) void scan_k(
    const int* __restrict__ text, const int* __restrict__ w2s)
{
    extern __shared__ float sm[];
    float* potT = sm;                  // 255*64  [g][j][i] = trans[cs[g,i], cs[g+1,j]]
    float* obs  = sm + 255 * 64;       // 256*8
    int*   cs   = (int*)(obs + 256 * 8); // 256*8
    int b = blockIdx.x, tid = threadIdx.x;

    for (int idx = tid; idx < TN * SPW; idx += 256) {
        int t = idx >> 3, k = idx & 7;
        int w = text[b * TN + t];
        cs[idx]  = w2s[w * SPW + k];
        obs[idx] = g_pair[w * SPW + k];
    }
    __syncthreads();
    for (int idx = tid; idx < 255 * 64; idx += 256) {
        int g = idx >> 6, r = idx & 63;
        int i = r >> 3, j = r & 7;
        potT[(g << 6) + (j << 3) + i] =
            g_trans[(size_t)cs[(g << 3) + i] * CN + cs[((g + 1) << 3) + j]];
    }
    __syncthreads();

    if (tid < 8) {
        int j = tid;
        float an = g_startlp[cs[j]] + obs[j];
        float a[8];
        #pragma unroll
        for (int i = 0; i < 8; i++) a[i] = __shfl_sync(0xFFu, an, i);

        for (int t = 1; t < TN; t++) {
            const float4* p4 = (const float4*)(potT + ((t - 1) << 6) + (j << 3));
            float4 pA = p4[0], pB = p4[1];
            float m01 = fmaxf(a[0], a[1]), m23 = fmaxf(a[2], a[3]);
            float m45 = fmaxf(a[4], a[5]), m67 = fmaxf(a[6], a[7]);
            float m = fmaxf(fmaxf(m01, m23), fmaxf(m45, m67));
            float e0 = __expf(pA.x + a[0] - m), e1 = __expf(pA.y + a[1] - m);
            float e2 = __expf(pA.z + a[2] - m), e3 = __expf(pA.w + a[3] - m);
            float e4 = __expf(pB.x + a[4] - m), e5 = __expf(pB.y + a[5] - m);
            float e6 = __expf(pB.z + a[6] - m), e7 = __expf(pB.w + a[7] - m);
            float s = ((e0 + e1) + (e2 + e3)) + ((e4 + e5) + (e6 + e7));
            an = obs[(t << 3) + j] + m + __logf(s);
            #pragma unroll
            for (int i = 0; i < 8; i++) a[i] = __shfl_sync(0xFFu, an, i);
        }
        if (j == 0) {
            float m01 = fmaxf(a[0], a[1]), m23 = fmaxf(a[2], a[3]);
            float m45 = fmaxf(a[4], a[5]), m67 = fmaxf(a[6], a[7]);
            float m = fmaxf(fmaxf(m01, m23), fmaxf(m45, m67));
            float s = 0.f;
            #pragma unroll
            for (int i = 0; i < 8; i++) s += __expf(a[i] - m);
            g_ev[b] = m + __logf(s);
        }
    }
}

__global__ void final_k(float* __restrict__ out)
{
    if (threadIdx.x == 0) {
        float s = 0.f;
        #pragma unroll
        for (int b = 0; b < BN; b++) s += g_ev[b];
        out[0] = s;
    }
}

// ---------------------------------------------------------------------------
extern "C" void kernel_launch(void* const* d_in, const int* in_sizes, int n_in,
                              void* d_out, int out_size)
{
    const float* start_emb = (const float*)d_in[0];
    const float* start_l1w = (const float*)d_in[1];
    const float* start_l1b = (const float*)d_in[2];
    const float* start_l2w = (const float*)d_in[3];
    const float* start_l2b = (const float*)d_in[4];
    const float* start_ow  = (const float*)d_in[5];
    const float* start_ob  = (const float*)d_in[6];
    const float* state_emb = (const float*)d_in[7];
    const float* trans_l1w = (const float*)d_in[8];
    const float* trans_l1b = (const float*)d_in[9];
    const float* trans_l2w = (const float*)d_in[10];
    const float* trans_l2b = (const float*)d_in[11];
    const float* proj_w    = (const float*)d_in[12];
    const float* pret_emb  = (const float*)d_in[13];
    const float* term_l1w  = (const float*)d_in[14];
    const float* term_l1b  = (const float*)d_in[15];
    const float* term_l2w  = (const float*)d_in[16];
    const float* term_l2b  = (const float*)d_in[17];
    const float* term_ow   = (const float*)d_in[18];
    const float* term_ob   = (const float*)d_in[19];
    const int*   text      = (const int*)d_in[20];
    const int*   w2s       = (const int*)d_in[21];
    float* out = (float*)d_out;

    float *tmp, *hs, *ht, *hp, *trans;
    cudaGetSymbolAddress((void**)&tmp,   g_tmp);
    cudaGetSymbolAddress((void**)&hs,    g_hs);
    cudaGetSymbolAddress((void**)&ht,    g_ht);
    cudaGetSymbolAddress((void**)&hp,    g_hp);
    cudaGetSymbolAddress((void**)&trans, g_trans);

    dim3 blk(256);

    init_k<<<4, blk>>>();

    // start MLP + head
    gemm64<<<dim3(HN/64, CN/64), blk>>>(start_emb, start_l1w, start_l1b, nullptr, tmp, HN, HN, 1);
    gemm64<<<dim3(HN/64, CN/64), blk>>>(tmp, start_l2w, start_l2b, start_emb, hs, HN, HN, 1);
    start_head_k<<<CN/8, blk>>>(start_ow, start_ob);
    lsm_start_k<<<1, 1024>>>();

    // transition matrix
    gemm64<<<dim3(HN/64, CN/64), blk>>>(state_emb, trans_l1w, trans_l1b, nullptr, tmp, HN, HN, 1);
    gemm64<<<dim3(HN/64, CN/64), blk>>>(tmp, trans_l2w, trans_l2b, state_emb, ht, HN, HN, 1);
    gemm64<<<dim3(CN/64, CN/64), blk>>>(ht, proj_w, nullptr, nullptr, trans, HN, CN, 0);
    lsm_rows_k<<<CN, blk>>>();

    // emission (sparse: only valid (state, word) pairs)
    gemm64<<<dim3(HN/64, CN/64), blk>>>(pret_emb, term_l1w, term_l1b, nullptr, tmp, HN, HN, 1);
    gemm64<<<dim3(HN/64, CN/64), blk>>>(tmp, term_l2w, term_l2b, pret_emb, hp, HN, HN, 1);
    term_pair_k<<<VN, blk>>>(term_ow, term_ob, w2s);
    term_sum_k<<<(VN*SPW + 255)/256, blk>>>(w2s);
    denom_k<<<(CN + 255)/256, blk>>>();
    elog_k<<<(VN*SPW + 255)/256, blk>>>(w2s);

    // forward scan + final sum
    int smem_bytes = (255*64 + 256*8) * 4 + 256*8*4;
    cudaFuncSetAttribute(scan_k, cudaFuncAttributeMaxDynamicSharedMemorySize, smem_bytes);
    scan_k<<<BN, blk, smem_bytes>>>(text, w2s);
    final_k<<<1, 32>>>(out);
}

// round 2
// speedup vs baseline: 2.0221x; 2.0221x over previous
#include <cuda_runtime.h>
#include <cuda_bf16.h>
#include <math.h>

#define CN 1024
#define HN 512
#define VN 32000
#define BN 16
#define TN 256
#define SPW 8

// ------------------------- scratch (static device memory; no allocs) -------
__device__ __nv_bfloat16 g_tmpb[3 * CN * HN];  // relu(layer1) per chain, bf16
__device__ float g_hs[CN * HN];                // start residual out
__device__ float g_ht[CN * HN];                // trans residual out
__device__ __nv_bfloat16 g_hpb[CN * HN];       // term residual out (bf16)
__device__ float g_sl[CN];
__device__ float g_startlp[CN];
__device__ float g_trans[CN * CN];
__device__ float g_pair[VN * SPW];  // pair logits, later emission log-probs in-place
__device__ unsigned g_maxk[CN];
__device__ float g_sumb[CN];
__device__ float g_denom[CN];
__device__ float g_ev[BN];

// monotonic float<->uint encoding for atomicMax on floats
__device__ __forceinline__ unsigned enc_f(float f) {
    int i = __float_as_int(f);
    return (unsigned)(i ^ ((i >> 31) | 0x80000000));
}
__device__ __forceinline__ float dec_f(unsigned u) {
    int i = (u & 0x80000000u) ? (int)(u ^ 0x80000000u) : ~(int)u;
    return __int_as_float(i);
}

// ---------------------------------------------------------------------------
// bf16 tensor-core GEMM core: out[m,n] = post( sum_k A[m,k]*W[n,k] )
//   post = (+bias[n]) -> relu -> (+res[m,n]); writes fp32 and/or bf16.
// CTA tile 64x64, 4 warps (2x2), warp tile 32x32, K-step 32.
// mma.sync.aligned.m16n8k16.row.col.f32.bf16.bf16.f32
// ---------------------------------------------------------------------------
__device__ __forceinline__ void mma16816(float* d, const unsigned* a, const unsigned* b) {
    asm volatile(
        "mma.sync.aligned.m16n8k16.row.col.f32.bf16.bf16.f32 "
        "{%0,%1,%2,%3}, {%4,%5,%6,%7}, {%8,%9}, {%0,%1,%2,%3};\n"
        : "+f"(d[0]), "+f"(d[1]), "+f"(d[2]), "+f"(d[3])
        : "r"(a[0]), "r"(a[1]), "r"(a[2]), "r"(a[3]), "r"(b[0]), "r"(b[1]));
}

#define SSTRIDE 40  // bf16 elements per smem row (80B) -> conflict-free frag loads

template <bool ABF>
__device__ __forceinline__ void gemm_core(
    const float* __restrict__ Af, const __nv_bfloat16* __restrict__ Ab,
    const float* __restrict__ W, const float* __restrict__ bias,
    const float* __restrict__ res, float* __restrict__ outF,
    __nv_bfloat16* __restrict__ outB, int N, int K, int relu)
{
    __shared__ __nv_bfloat16 sA[64 * SSTRIDE];
    __shared__ __nv_bfloat16 sB[64 * SSTRIDE];

    const int t = threadIdx.x;
    const int lane = t & 31, warp = t >> 5;
    const int wm = warp >> 1, wn = warp & 1;
    const int row0 = blockIdx.y * 64, col0 = blockIdx.x * 64;
    const int lr = lane >> 2, lc = lane & 3;

    float acc[2][4][4];
#pragma unroll
    for (int mt = 0; mt < 2; mt++)
#pragma unroll
        for (int nt = 0; nt < 4; nt++)
#pragma unroll
            for (int q = 0; q < 4; q++) acc[mt][nt][q] = 0.f;

    float4 pa[4];
    uint2 pab[4];
    float4 pw[4];

    // prefetch first tile
#pragma unroll
    for (int i = 0; i < 4; i++) {
        int id = i * 128 + t, r = id >> 3, c4 = id & 7;
        if (ABF)
            pab[i] = *(const uint2*)(Ab + (size_t)(row0 + r) * K + c4 * 4);
        else
            pa[i] = *(const float4*)(Af + (size_t)(row0 + r) * K + c4 * 4);
        pw[i] = *(const float4*)(W + (size_t)(col0 + r) * K + c4 * 4);
    }

    const int NT = K / 32;
    for (int kt = 0; kt < NT; kt++) {
        // store staged tile to smem (convert fp32 -> bf16 if needed)
#pragma unroll
        for (int i = 0; i < 4; i++) {
            int id = i * 128 + t, r = id >> 3, c4 = id & 7;
            __nv_bfloat16* da = &sA[r * SSTRIDE + c4 * 4];
            if (ABF) {
                *(unsigned*)da = pab[i].x;
                *(unsigned*)(da + 2) = pab[i].y;
            } else {
                *(__nv_bfloat162*)da = __float22bfloat162_rn(make_float2(pa[i].x, pa[i].y));
                *(__nv_bfloat162*)(da + 2) = __float22bfloat162_rn(make_float2(pa[i].z, pa[i].w));
            }
            __nv_bfloat16* dw = &sB[r * SSTRIDE + c4 * 4];
            *(__nv_bfloat162*)dw = __float22bfloat162_rn(make_float2(pw[i].x, pw[i].y));
            *(__nv_bfloat162*)(dw + 2) = __float22bfloat162_rn(make_float2(pw[i].z, pw[i].w));
        }
        __syncthreads();

        // prefetch next tile while computing this one
        int kn = (kt + 1) * 32;
        if (kn < K) {
#pragma unroll
            for (int i = 0; i < 4; i++) {
                int id = i * 128 + t, r = id >> 3, c4 = id & 7;
                if (ABF)
                    pab[i] = *(const uint2*)(Ab + (size_t)(row0 + r) * K + kn + c4 * 4);
                else
                    pa[i] = *(const float4*)(Af + (size_t)(row0 + r) * K + kn + c4 * 4);
                pw[i] = *(const float4*)(W + (size_t)(col0 + r) * K + kn + c4 * 4);
            }
        }

#pragma unroll
        for (int kk = 0; kk < 2; kk++) {
            unsigned af[2][4], bfr[4][2];
            int kb = kk * 16 + lc * 2;
#pragma unroll
            for (int mt = 0; mt < 2; mt++) {
                const __nv_bfloat16* p = &sA[(wm * 32 + mt * 16 + lr) * SSTRIDE + kb];
                af[mt][0] = *(const unsigned*)p;
                af[mt][1] = *(const unsigned*)(p + 8 * SSTRIDE);
                af[mt][2] = *(const unsigned*)(p + 8);
                af[mt][3] = *(const unsigned*)(p + 8 * SSTRIDE + 8);
            }
#pragma unroll
            for (int nt = 0; nt < 4; nt++) {
                const __nv_bfloat16* p = &sB[(wn * 32 + nt * 8 + lr) * SSTRIDE + kb];
                bfr[nt][0] = *(const unsigned*)p;
                bfr[nt][1] = *(const unsigned*)(p + 8);
            }
#pragma unroll
            for (int mt = 0; mt < 2; mt++)
#pragma unroll
                for (int nt = 0; nt < 4; nt++) mma16816(acc[mt][nt], af[mt], bfr[nt]);
        }
        __syncthreads();
    }

    // epilogue: bias -> relu -> +res, write fp32 / bf16
#pragma unroll
    for (int mt = 0; mt < 2; mt++)
#pragma unroll
        for (int nt = 0; nt < 4; nt++) {
            int gr = row0 + wm * 32 + mt * 16 + lr;
            int gc = col0 + wn * 32 + nt * 8 + lc * 2;
            float2 b2 = make_float2(0.f, 0.f);
            if (bias) b2 = *(const float2*)(bias + gc);
#pragma unroll
            for (int h = 0; h < 2; h++) {
                int r_ = gr + h * 8;
                float v0 = acc[mt][nt][h * 2 + 0] + b2.x;
                float v1 = acc[mt][nt][h * 2 + 1] + b2.y;
                if (relu) { v0 = fmaxf(v0, 0.f); v1 = fmaxf(v1, 0.f); }
                if (res) {
                    float2 r2 = *(const float2*)(res + (size_t)r_ * N + gc);
                    v0 += r2.x; v1 += r2.y;
                }
                if (outF) *(float2*)(outF + (size_t)r_ * N + gc) = make_float2(v0, v1);
                if (outB)
                    *(__nv_bfloat162*)(outB + (size_t)r_ * N + gc) =
                        __float22bfloat162_rn(make_float2(v0, v1));
            }
        }
}

// layer 1 (batched over z=3 chains): tmpb[z] = relu(emb[z] @ l1w[z]^T + l1b[z]), bf16
__global__ __launch_bounds__(128) void gemm_l1_k(
    const float* A0, const float* A1, const float* A2,
    const float* W0, const float* W1, const float* W2,
    const float* B0, const float* B1, const float* B2)
{
    int z = blockIdx.z;
    const float* A = z == 0 ? A0 : (z == 1 ? A1 : A2);
    const float* W = z == 0 ? W0 : (z == 1 ? W1 : W2);
    const float* B = z == 0 ? B0 : (z == 1 ? B1 : B2);
    gemm_core<false>(A, nullptr, W, B, nullptr, nullptr,
                     g_tmpb + (size_t)z * CN * HN, HN, HN, 1);
}

// layer 2 (batched): out[z] = emb[z] + relu(tmpb[z] @ l2w[z]^T + l2b[z])
__global__ __launch_bounds__(128) void gemm_l2_k(
    const float* W0, const float* W1, const float* W2,
    const float* B0, const float* B1, const float* B2,
    const float* R0, const float* R1, const float* R2)
{
    int z = blockIdx.z;
    const float* W = z == 0 ? W0 : (z == 1 ? W1 : W2);
    const float* B = z == 0 ? B0 : (z == 1 ? B1 : B2);
    const float* R = z == 0 ? R0 : (z == 1 ? R1 : R2);
    float* oF = z == 0 ? g_hs : (z == 1 ? g_ht : nullptr);
    __nv_bfloat16* oB = z == 2 ? g_hpb : nullptr;
    gemm_core<true>(nullptr, g_tmpb + (size_t)z * CN * HN, W, B, R, oF, oB, HN, HN, 1);
}

// trans projection: g_trans = g_ht @ proj_w^T  (1024x1024x512)
__global__ __launch_bounds__(128) void gemm_proj_k(const float* W)
{
    gemm_core<false>(g_ht, nullptr, W, nullptr, nullptr, g_trans, nullptr, CN, HN, 0);
}

// ---------------------------------------------------------------------------
// start head: g_sl[c] = dot(g_hs[c,:], ow) + ob
// ---------------------------------------------------------------------------
__global__ __launch_bounds__(256) void start_head_k(
    const float* __restrict__ ow, const float* __restrict__ ob)
{
    int warp = threadIdx.x >> 5, lane = threadIdx.x & 31;
    int c = blockIdx.x * 8 + warp;
    const float4* h4 = (const float4*)(g_hs + (size_t)c * HN);
    const float4* w4 = (const float4*)ow;
    float s = 0.f;
#pragma unroll
    for (int i = lane; i < HN / 4; i += 32) {
        float4 a = h4[i], w = w4[i];
        s = fmaf(a.x, w.x, s); s = fmaf(a.y, w.y, s);
        s = fmaf(a.z, w.z, s); s = fmaf(a.w, w.w, s);
    }
#pragma unroll
    for (int o = 16; o; o >>= 1) s += __shfl_xor_sync(0xffffffffu, s, o);
    if (lane == 0) g_sl[c] = s + ob[0];
}

// log_softmax over 1024 start logits
__global__ __launch_bounds__(1024) void lsm_start_k()
{
    __shared__ float red[32];
    __shared__ float bc;
    int t = threadIdx.x;
    float v = g_sl[t];
    float m = v;
#pragma unroll
    for (int o = 16; o; o >>= 1) m = fmaxf(m, __shfl_xor_sync(0xffffffffu, m, o));
    if ((t & 31) == 0) red[t >> 5] = m;
    __syncthreads();
    if (t < 32) {
        float x = red[t];
#pragma unroll
        for (int o = 16; o; o >>= 1) x = fmaxf(x, __shfl_xor_sync(0xffffffffu, x, o));
        if (t == 0) bc = x;
    }
    __syncthreads();
    m = bc;
    float e = __expf(v - m);
    float s = e;
#pragma unroll
    for (int o = 16; o; o >>= 1) s += __shfl_xor_sync(0xffffffffu, s, o);
    __syncthreads();
    if ((t & 31) == 0) red[t >> 5] = s;
    __syncthreads();
    if (t < 32) {
        float x = red[t];
#pragma unroll
        for (int o = 16; o; o >>= 1) x += __shfl_xor_sync(0xffffffffu, x, o);
        if (t == 0) bc = x;
    }
    __syncthreads();
    g_startlp[t] = v - m - __logf(bc);
}

// per-row log_softmax of g_trans (1024x1024)
__global__ __launch_bounds__(256) void lsm_rows_k()
{
    __shared__ float red[8];
    __shared__ float bc;
    int row = blockIdx.x, t = threadIdx.x;
    float4* p4 = (float4*)(g_trans + (size_t)row * CN);
    float4 v = p4[t];
    float m = fmaxf(fmaxf(v.x, v.y), fmaxf(v.z, v.w));
#pragma unroll
    for (int o = 16; o; o >>= 1) m = fmaxf(m, __shfl_xor_sync(0xffffffffu, m, o));
    if ((t & 31) == 0) red[t >> 5] = m;
    __syncthreads();
    if (t < 8) {
        float x = red[t];
#pragma unroll
        for (int o = 4; o; o >>= 1) x = fmaxf(x, __shfl_xor_sync(0xffu, x, o));
        if (t == 0) bc = x;
    }
    __syncthreads();
    m = bc;
    float e = __expf(v.x - m) + __expf(v.y - m) + __expf(v.z - m) + __expf(v.w - m);
#pragma unroll
    for (int o = 16; o; o >>= 1) e += __shfl_xor_sync(0xffffffffu, e, o);
    __syncthreads();
    if ((t & 31) == 0) red[t >> 5] = e;
    __syncthreads();
    if (t < 8) {
        float x = red[t];
#pragma unroll
        for (int o = 4; o; o >>= 1) x += __shfl_xor_sync(0xffu, x, o);
        if (t == 0) bc = x;
    }
    __syncthreads();
    float lz = m + __logf(bc);
    p4[t] = make_float4(v.x - lz, v.y - lz, v.z - lz, v.w - lz);
}

// ---------------------------------------------------------------------------
// term sparse stage
// ---------------------------------------------------------------------------
__global__ void init_k()
{
    int i = blockIdx.x * 256 + threadIdx.x;
    if (i < CN) { g_maxk[i] = 0u; g_sumb[i] = 0.f; }  // key 0 == -inf
}

// one block per word: dot(hpb[c] (bf16), term_ow[v]) + ob[v] for its 8 states
__global__ __launch_bounds__(256) void term_pair_k(
    const float* __restrict__ tow, const float* __restrict__ tob,
    const int* __restrict__ w2s)
{
    __shared__ float ws[HN];
    __shared__ int cs[SPW];
    int v = blockIdx.x, tid = threadIdx.x;
    for (int i = tid; i < HN / 4; i += 256)
        ((float4*)ws)[i] = ((const float4*)(tow + (size_t)v * HN))[i];
    if (tid < SPW) cs[tid] = w2s[v * SPW + tid];
    __syncthreads();
    int warp = tid >> 5, lane = tid & 31;
    int c = cs[warp];
    const __nv_bfloat162* h2 = (const __nv_bfloat162*)(g_hpb + (size_t)c * HN);
    const float2* w2 = (const float2*)ws;
    float s = 0.f;
#pragma unroll
    for (int i = lane; i < HN / 2; i += 32) {
        __nv_bfloat162 h = h2[i];
        float2 w = w2[i];
        s = fmaf(__low2float(h), w.x, s);
        s = fmaf(__high2float(h), w.y, s);
    }
#pragma unroll
    for (int o = 16; o; o >>= 1) s += __shfl_xor_sync(0xffffffffu, s, o);
    if (lane == 0) {
        float logit = s + tob[v];
        g_pair[v * SPW + warp] = logit;
        bool dup = false;
        for (int k2 = 0; k2 < warp; k2++) if (cs[k2] == c) dup = true;
        if (!dup) atomicMax(&g_maxk[c], enc_f(logit));
    }
}

__global__ void term_sum_k(const int* __restrict__ w2s)
{
    int idx = blockIdx.x * 256 + threadIdx.x;
    if (idx >= VN * SPW) return;
    int v = idx >> 3, k = idx & 7;
    int c = w2s[idx];
    for (int k2 = 0; k2 < k; k2++) if (w2s[(v << 3) + k2] == c) return;
    atomicAdd(&g_sumb[c], __expf(g_pair[idx] - dec_f(g_maxk[c])));
}

__global__ void denom_k()
{
    int c = blockIdx.x * 256 + threadIdx.x;
    if (c < CN) g_denom[c] = dec_f(g_maxk[c]) + __logf(g_sumb[c]);
}

__global__ void elog_k(const int* __restrict__ w2s)
{
    int idx = blockIdx.x * 256 + threadIdx.x;
    if (idx >= VN * SPW) return;
    g_pair[idx] -= g_denom[w2s[idx]];  // now emission log-prob per (word, k)
}

// ---------------------------------------------------------------------------
// forward scan: one block per batch
// ---------------------------------------------------------------------------
__global__ __launch_bounds__(256) void scan_k(
    const int* __restrict__ text, const int* __restrict__ w2s)
{
    extern __shared__ float sm[];
    float* potT = sm;                    // 255*64  [g][j][i]
    float* obs = sm + 255 * 64;          // 256*8
    int* cs = (int*)(obs + 256 * 8);     // 256*8
    int b = blockIdx.x, tid = threadIdx.x;

    for (int idx = tid; idx < TN * SPW; idx += 256) {
        int t = idx >> 3, k = idx & 7;
        int w = text[b * TN + t];
        cs[idx] = w2s[w * SPW + k];
        obs[idx] = g_pair[w * SPW + k];
    }
    __syncthreads();
    for (int idx = tid; idx < 255 * 64; idx += 256) {
        int g = idx >> 6, r = idx & 63;
        int i = r >> 3, j = r & 7;
        potT[(g << 6) + (j << 3) + i] =
            g_trans[(size_t)cs[(g << 3) + i] * CN + cs[((g + 1) << 3) + j]];
    }
    __syncthreads();

    if (tid < 8) {
        int j = tid;
        float an = g_startlp[cs[j]] + obs[j];
        float a[8];
#pragma unroll
        for (int i = 0; i < 8; i++) a[i] = __shfl_sync(0xFFu, an, i);

        for (int t = 1; t < TN; t++) {
            const float4* p4 = (const float4*)(potT + ((t - 1) << 6) + (j << 3));
            float4 pA = p4[0], pB = p4[1];
            float m01 = fmaxf(a[0], a[1]), m23 = fmaxf(a[2], a[3]);
            float m45 = fmaxf(a[4], a[5]), m67 = fmaxf(a[6], a[7]);
            float m = fmaxf(fmaxf(m01, m23), fmaxf(m45, m67));
            float e0 = __expf(pA.x + a[0] - m), e1 = __expf(pA.y + a[1] - m);
            float e2 = __expf(pA.z + a[2] - m), e3 = __expf(pA.w + a[3] - m);
            float e4 = __expf(pB.x + a[4] - m), e5 = __expf(pB.y + a[5] - m);
            float e6 = __expf(pB.z + a[6] - m), e7 = __expf(pB.w + a[7] - m);
            float s = ((e0 + e1) + (e2 + e3)) + ((e4 + e5) + (e6 + e7));
            an = obs[(t << 3) + j] + m + __logf(s);
#pragma unroll
            for (int i = 0; i < 8; i++) a[i] = __shfl_sync(0xFFu, an, i);
        }
        if (j == 0) {
            float m01 = fmaxf(a[0], a[1]), m23 = fmaxf(a[2], a[3]);
            float m45 = fmaxf(a[4], a[5]), m67 = fmaxf(a[6], a[7]);
            float m = fmaxf(fmaxf(m01, m23), fmaxf(m45, m67));
            float s = 0.f;
#pragma unroll
            for (int i = 0; i < 8; i++) s += __expf(a[i] - m);
            g_ev[b] = m + __logf(s);
        }
    }
}

__global__ void final_k(float* __restrict__ out)
{
    if (threadIdx.x == 0) {
        float s = 0.f;
#pragma unroll
        for (int b = 0; b < BN; b++) s += g_ev[b];
        out[0] = s;
    }
}

// ---------------------------------------------------------------------------
extern "C" void kernel_launch(void* const* d_in, const int* in_sizes, int n_in,
                              void* d_out, int out_size)
{
    const float* start_emb = (const float*)d_in[0];
    const float* start_l1w = (const float*)d_in[1];
    const float* start_l1b = (const float*)d_in[2];
    const float* start_l2w = (const float*)d_in[3];
    const float* start_l2b = (const float*)d_in[4];
    const float* start_ow  = (const float*)d_in[5];
    const float* start_ob  = (const float*)d_in[6];
    const float* state_emb = (const float*)d_in[7];
    const float* trans_l1w = (const float*)d_in[8];
    const float* trans_l1b = (const float*)d_in[9];
    const float* trans_l2w = (const float*)d_in[10];
    const float* trans_l2b = (const float*)d_in[11];
    const float* proj_w    = (const float*)d_in[12];
    const float* pret_emb  = (const float*)d_in[13];
    const float* term_l1w  = (const float*)d_in[14];
    const float* term_l1b  = (const float*)d_in[15];
    const float* term_l2w  = (const float*)d_in[16];
    const float* term_l2b  = (const float*)d_in[17];
    const float* term_ow   = (const float*)d_in[18];
    const float* term_ob   = (const float*)d_in[19];
    const int*   text      = (const int*)d_in[20];
    const int*   w2s       = (const int*)d_in[21];
    float* out = (float*)d_out;

    dim3 blk(256);

    init_k<<<4, blk>>>();

    // residual MLPs on tensor cores (3 chains batched in z)
    gemm_l1_k<<<dim3(HN / 64, CN / 64, 3), 128>>>(
        start_emb, state_emb, pret_emb,
        start_l1w, trans_l1w, term_l1w,
        start_l1b, trans_l1b, term_l1b);
    gemm_l2_k<<<dim3(HN / 64, CN / 64, 3), 128>>>(
        start_l2w, trans_l2w, term_l2w,
        start_l2b, trans_l2b, term_l2b,
        start_emb, state_emb, pret_emb);

    // start head + log_softmax
    start_head_k<<<CN / 8, blk>>>(start_ow, start_ob);
    lsm_start_k<<<1, 1024>>>();

    // transition matrix + row log_softmax
    gemm_proj_k<<<dim3(CN / 64, CN / 64, 1), 128>>>(proj_w);
    lsm_rows_k<<<CN, blk>>>();

    // emission (sparse: only valid (state, word) pairs)
    term_pair_k<<<VN, blk>>>(term_ow, term_ob, w2s);
    term_sum_k<<<(VN * SPW + 255) / 256, blk>>>(w2s);
    denom_k<<<(CN + 255) / 256, blk>>>();
    elog_k<<<(VN * SPW + 255) / 256, blk>>>(w2s);

    // forward scan + final sum
    int smem_bytes = (255 * 64 + 256 * 8) * 4 + 256 * 8 * 4;
    cudaFuncSetAttribute(scan_k, cudaFuncAttributeMaxDynamicSharedMemorySize, smem_bytes);
    scan_k<<<BN, blk, smem_bytes>>>(text, w2s);
    final_k<<<1, 32>>>(out);
}